// round 16
// baseline (speedup 1.0000x reference)
#include <cuda_runtime.h>
#include <cuda_fp16.h>
#include <math.h>
#include <stdint.h>

// Problem constants
#define BATCH 4
#define SEQ   2048
#define EMB   1024
#define HEADS 16
#define DHEAD 64
#define MTOT  (BATCH*SEQ)      // 8192
#define FFN   (4*EMB)          // 4096

#if defined(__CUDA_ARCH__) && (defined(__CUDA_ARCH_FEAT_SM103_ALL) || defined(__CUDA_ARCH_FEAT_SM100_ALL))
#define TC_OK 1
#else
#define TC_OK 0
#endif

// ---------------- scratch (no allocs allowed) ----------------
__device__ __half g_lnx [(size_t)MTOT*EMB];
__device__ __half g_qkv [(size_t)MTOT*3*EMB];
__device__ __half g_vt  [(size_t)BATCH*HEADS*DHEAD*SEQ];   // V^T per (b,h): [64 d][2048 s]
__device__ __half g_ctx [(size_t)MTOT*EMB];
__device__ float  g_h   [(size_t)MTOT*EMB];
__device__ __half g_mid [(size_t)MTOT*FFN];
__device__ __half g_wqkv_t[(size_t)3*EMB*EMB];
__device__ __half g_wo_t  [(size_t)EMB*EMB];
__device__ __half g_w1_t  [(size_t)FFN*EMB];
__device__ __half g_w2_t  [(size_t)EMB*FFN];

// ---------------- helpers ----------------
__device__ __forceinline__ uint32_t smem_u32(const void* p) {
    uint32_t a;
    asm("{ .reg .u64 t; cvta.to.shared.u64 t, %1; cvt.u32.u64 %0, t; }" : "=r"(a) : "l"(p));
    return a;
}
__device__ __forceinline__ float ex2(float x) {
    float r;
    asm("ex2.approx.f32 %0, %1;" : "=f"(r) : "f"(x));
    return r;
}
#define SWZ(o) ((o) ^ (((o) >> 3) & 0x70))

#define MBAR_INIT(a, c) asm volatile("mbarrier.init.shared.b64 [%0], %1;" :: "r"(a), "r"(c) : "memory")
#define MBAR_INVAL(a)   asm volatile("mbarrier.inval.shared.b64 [%0];" :: "r"(a) : "memory")
#define MBAR_WAIT(a, ph) do { \
    uint32_t _m = (a); uint32_t _p = (ph); uint32_t _d; \
    asm volatile("{ .reg .pred p; mbarrier.try_wait.parity.acquire.cta.shared::cta.b64 p, [%1], %2; selp.b32 %0,1,0,p; }" \
        : "=r"(_d) : "r"(_m), "r"(_p) : "memory"); \
    if (!_d) { \
        asm volatile("{ .reg .pred P1; WL_%=: mbarrier.try_wait.parity.acquire.cta.shared::cta.b64 P1, [%0], %1, 0x989680; @P1 bra.uni WD_%=; bra.uni WL_%=; WD_%=: }" \
            :: "r"(_m), "r"(_p) : "memory"); \
    } } while (0)

#define CPA16(dst, src) asm volatile("cp.async.cg.shared.global [%0], [%1], 16;" :: "r"(dst), "l"(src) : "memory")
#define CPA_COMMIT() asm volatile("cp.async.commit_group;" ::: "memory")
#define CPA_WAIT2()  asm volatile("cp.async.wait_group 2;" ::: "memory")
#define CPA_WAIT1()  asm volatile("cp.async.wait_group 1;" ::: "memory")
#define CPA_WAIT0()  asm volatile("cp.async.wait_group 0;" ::: "memory")

#if TC_OK
__device__ __forceinline__ uint32_t elect1() {
    uint32_t p;
    asm volatile("{ .reg .pred p; elect.sync _|p, 0xFFFFFFFF; selp.b32 %0,1,0,p; }" : "=r"(p));
    return p;
}
// K-major SW128: LBO=1, SBO=64 (proven)
__device__ __forceinline__ uint64_t make_desc_sw128(uint32_t addr) {
    const uint64_t base = (2ull << 61) | (1ull << 46) | (64ull << 32) | (1ull << 16);
    return base | ((uint64_t)(addr >> 4) & 0x3FFF);
}
#define LDTM_X32(r, addr) \
    asm volatile("tcgen05.ld.sync.aligned.32x32b.x32.b32 " \
        "{%0,%1,%2,%3,%4,%5,%6,%7,%8,%9,%10,%11,%12,%13,%14,%15," \
        "%16,%17,%18,%19,%20,%21,%22,%23,%24,%25,%26,%27,%28,%29,%30,%31}, [%32];" \
        : "=r"((r)[0]),"=r"((r)[1]),"=r"((r)[2]),"=r"((r)[3]),"=r"((r)[4]),"=r"((r)[5]),"=r"((r)[6]),"=r"((r)[7]), \
          "=r"((r)[8]),"=r"((r)[9]),"=r"((r)[10]),"=r"((r)[11]),"=r"((r)[12]),"=r"((r)[13]),"=r"((r)[14]),"=r"((r)[15]), \
          "=r"((r)[16]),"=r"((r)[17]),"=r"((r)[18]),"=r"((r)[19]),"=r"((r)[20]),"=r"((r)[21]),"=r"((r)[22]),"=r"((r)[23]), \
          "=r"((r)[24]),"=r"((r)[25]),"=r"((r)[26]),"=r"((r)[27]),"=r"((r)[28]),"=r"((r)[29]),"=r"((r)[30]),"=r"((r)[31]) \
        : "r"(addr))

__device__ __forceinline__ void mma_f16_ss(uint32_t d, uint64_t ad, uint64_t bd,
                                           uint32_t idesc, uint32_t en) {
    asm volatile("{\n\t.reg .pred p;\n\tsetp.ne.u32 p, %5, 0;\n\t"
        "tcgen05.mma.cta_group::1.kind::f16 [%0], %1, %2, %3, {%4,%4,%4,%4}, p;\n\t}"
        :: "r"(d), "l"(ad), "l"(bd), "r"(idesc), "r"(0u), "r"(en) : "memory");
}
#endif

// ---------------- merged weight prep: fp16 transposed [N,K] ----------------
__global__ void prep_weights_kernel(const float* __restrict__ Wq, const float* __restrict__ Wk,
                                    const float* __restrict__ Wv, const float* __restrict__ Wo,
                                    const float* __restrict__ W1, const float* __restrict__ W2,
                                    __half* __restrict__ wqkv_t, __half* __restrict__ wo_t,
                                    __half* __restrict__ w1_t, __half* __restrict__ w2_t) {
    __shared__ float t[32][33];
    int id = blockIdx.x;
    const float* W; __half* WT; int K, N, n0, k0;
    if (id < 4096) {
        int w = id >> 10; id &= 1023;
        K = EMB; N = EMB;
        W  = (w == 0) ? Wq : (w == 1) ? Wk : (w == 2) ? Wv : Wo;
        WT = (w < 3) ? (wqkv_t + (size_t)w * EMB * EMB) : wo_t;
        n0 = (id & 31) * 32; k0 = (id >> 5) * 32;
    } else if (id < 8192) {
        id -= 4096; K = EMB; N = FFN; W = W1; WT = w1_t;
        n0 = (id & 127) * 32; k0 = (id >> 7) * 32;
    } else {
        id -= 8192; K = FFN; N = EMB; W = W2; WT = w2_t;
        n0 = (id & 31) * 32; k0 = (id >> 5) * 32;
    }
    const int tx = threadIdx.x & 31, ty = threadIdx.x >> 5;
    #pragma unroll
    for (int j = 0; j < 32; j += 8)
        t[ty + j][tx] = W[(size_t)(k0 + ty + j) * N + n0 + tx];
    __syncthreads();
    #pragma unroll
    for (int j = 0; j < 32; j += 8)
        WT[(size_t)(n0 + ty + j) * K + k0 + tx] = __float2half_rn(t[tx][ty + j]);
}

// ---------------- V transpose: QKV V-part -> [bh][64 d][2048 s] fp16 ----------------
#define QKVS (3*EMB)
__global__ void vt_kernel(const __half* __restrict__ QKV, __half* __restrict__ vt) {
    __shared__ __align__(16) __half t[64][72];
    const int tid = threadIdx.x;
    const int bh = blockIdx.y, s0 = blockIdx.x * 64;
    const int b = bh >> 4, h = bh & 15;
    const __half* src = QKV + (size_t)(b * SEQ + s0) * QKVS + 2 * EMB + h * DHEAD;
    #pragma unroll
    for (int p = 0; p < 2; p++) {
        int idx = tid + p * 256;
        int r = idx >> 3, g = idx & 7;
        *(uint4*)&t[r][g * 8] = *(const uint4*)(src + (size_t)r * QKVS + g * 8);
    }
    __syncthreads();
    __half* dst = vt + (size_t)bh * DHEAD * SEQ + s0;
    #pragma unroll
    for (int p = 0; p < 2; p++) {
        int idx = tid + p * 256;
        int d = idx >> 3, g = idx & 7;
        __half tmp[8];
        #pragma unroll
        for (int i = 0; i < 8; i++) tmp[i] = t[g * 8 + i][d];
        *(uint4*)(dst + (size_t)d * SEQ + g * 8) = *(uint4*)tmp;
    }
}

// ---------------- LayerNorm -> fp16 out ----------------
__device__ __forceinline__ float warp_sum(float v) {
    #pragma unroll
    for (int o = 16; o > 0; o >>= 1) v += __shfl_xor_sync(0xffffffffu, v, o);
    return v;
}

__global__ void layernorm_kernel(const float* __restrict__ x,
                                 const float* __restrict__ gamma,
                                 const float* __restrict__ beta,
                                 __half* __restrict__ out) {
    const int row = blockIdx.x;
    const float* xr = x + (size_t)row * EMB;
    float s = 0.f, s2 = 0.f;
    for (int i = threadIdx.x; i < EMB; i += blockDim.x) {
        float v = xr[i];
        s += v; s2 += v * v;
    }
    s = warp_sum(s); s2 = warp_sum(s2);
    __shared__ float sh[2][8];
    int lane = threadIdx.x & 31, wid = threadIdx.x >> 5;
    if (lane == 0) { sh[0][wid] = s; sh[1][wid] = s2; }
    __syncthreads();
    if (wid == 0) {
        float a = (lane < 8) ? sh[0][lane] : 0.f;
        float b = (lane < 8) ? sh[1][lane] : 0.f;
        a = warp_sum(a); b = warp_sum(b);
        if (lane == 0) { sh[0][0] = a; sh[1][0] = b; }
    }
    __syncthreads();
    float mean = sh[0][0] * (1.0f / EMB);
    float var  = sh[1][0] * (1.0f / EMB) - mean * mean;
    float inv  = rsqrtf(var + 1e-5f);
    __half* outr = out + (size_t)row * EMB;
    for (int i = threadIdx.x; i < EMB; i += blockDim.x) {
        outr[i] = __float2half_rn(gamma[i] * ((xr[i] - mean) * inv) + beta[i]);
    }
}

// ---------------- tcgen05 fp16 GEMM: 256x256 tile, BK=64, 3-stage cp.async (R13 proven) ----------------
#define BM 256
#define BN 256
#define BK 64
#define ABYTES (BM*128)
#define BBYTES (BN*128)
#define BUFBYTES (ABYTES+BBYTES)
#define NSTAGE 3
#define SMEM_DYN (NSTAGE*BUFBYTES + 1024)

#define IDESC_F16 ((1u << 4) | ((BN / 8) << 17) | (8u << 24))

template<bool GELU, bool BIAS, bool RES, bool OUT_F16>
__global__ void __launch_bounds__(256, 1)
tc_gemm(const __half* __restrict__ A, const __half* __restrict__ BT,
        float* __restrict__ C, int M, int N, int K,
        const float* __restrict__ bias, const float* __restrict__ res) {
#if TC_OK
    extern __shared__ char sm_raw[];
    __shared__ uint32_t s_tmem;
    __shared__ __align__(8) uint64_t s_mbar[NSTAGE];

    const int tid = threadIdx.x, wid = tid >> 5, lane = tid & 31;
    const int bm = blockIdx.y * BM, bn = blockIdx.x * BN;

    uint32_t smb_raw = smem_u32(sm_raw);
    uint32_t smb = (smb_raw + 1023u) & ~1023u;
    char* sm = sm_raw + (smb - smb_raw);
    uint32_t mbar0 = smem_u32(&s_mbar[0]);

    if (wid == 4) {
        asm volatile("tcgen05.alloc.cta_group::1.sync.aligned.shared::cta.b32 [%0], %1;"
                     :: "r"(smem_u32(&s_tmem)), "r"(512) : "memory");
    }
    if (tid == 0) { MBAR_INIT(mbar0, 1); MBAR_INIT(mbar0 + 8, 1); MBAR_INIT(mbar0 + 16, 1); }
    __syncthreads();
    const uint32_t tmem = s_tmem;

    const int am = tid >> 3, akq = tid & 7;
    const uint32_t sw0 = SWZ((uint32_t)(am * 128 + akq * 16));
    const int KIT = K / BK;

    #define ISSUE(j, stb) do { \
        const __half* ap = A + (size_t)(bm + am) * K + (j) * BK + akq * 8; \
        _Pragma("unroll") \
        for (int p = 0; p < 8; p++) \
            CPA16(smb + (stb) + p * 4096 + sw0, ap + (size_t)(p * 32) * K); \
        const __half* bp = BT + (size_t)(bn + am) * K + (j) * BK + akq * 8; \
        _Pragma("unroll") \
        for (int p = 0; p < 8; p++) \
            CPA16(smb + (stb) + ABYTES + p * 4096 + sw0, bp + (size_t)(p * 32) * K); \
    } while (0)

    #pragma unroll
    for (int j = 0; j < NSTAGE; j++) {
        ISSUE(j, (uint32_t)j * BUFBYTES);
        CPA_COMMIT();
    }

    for (int i = 0; i < KIT; i++) {
        const int s3 = i % NSTAGE;
        const uint32_t stb = (uint32_t)s3 * BUFBYTES;

        CPA_WAIT2();
        __syncthreads();
        asm volatile("fence.proxy.async.shared::cta;" ::: "memory");

        if (wid == 4) {
            uint64_t ad0 = make_desc_sw128(smb + stb);
            uint64_t ad1 = make_desc_sw128(smb + stb + 16384);
            uint64_t bd  = make_desc_sw128(smb + stb + ABYTES);
            if (elect1()) {
                #pragma unroll
                for (int kk = 0; kk < 4; kk++) {
                    uint32_t en = (i > 0 || kk > 0) ? 1u : 0u;
                    mma_f16_ss(tmem, ad0 + kk * 2, bd + kk * 2, IDESC_F16, en);
                }
                #pragma unroll
                for (int kk = 0; kk < 4; kk++) {
                    uint32_t en = (i > 0 || kk > 0) ? 1u : 0u;
                    mma_f16_ss(tmem + 256, ad1 + kk * 2, bd + kk * 2, IDESC_F16, en);
                }
                asm volatile("tcgen05.commit.cta_group::1.mbarrier::arrive::one.shared::cluster.b64 [%0];"
                             :: "r"(mbar0 + 8 * s3) : "memory");
            }
        }

        const int j = i + NSTAGE;
        if (j < KIT) {
            MBAR_WAIT(mbar0 + 8 * s3, (i / NSTAGE) & 1);
            ISSUE(j, stb);
        }
        CPA_COMMIT();
    }
    #undef ISSUE

    MBAR_WAIT(mbar0 + 8 * ((KIT - 1) % NSTAGE), ((KIT - 1) / NSTAGE) & 1);
    asm volatile("tcgen05.fence::after_thread_sync;" ::: "memory");
    __syncthreads();

    // R13 epilogue: 2 M-halves x 2 column-halves, staged via padded SMEM (warps 0-3)
    #pragma unroll
    for (int mh = 0; mh < 2; mh++) {
        #pragma unroll
        for (int h = 0; h < 2; h++) {
            if (wid < 4) {
                #pragma unroll
                for (int c = 0; c < 4; c++) {
                    uint32_t r[32];
                    LDTM_X32(r, tmem + mh * 256 + h * 128 + c * 32);
                    asm volatile("tcgen05.wait::ld.sync.aligned;" ::: "memory");
                    char* row = sm + (wid * 32 + lane) * 528 + c * 128;
                    #pragma unroll
                    for (int j = 0; j < 8; j++) {
                        float4 v;
                        v.x = __uint_as_float(r[4 * j + 0]);
                        v.y = __uint_as_float(r[4 * j + 1]);
                        v.z = __uint_as_float(r[4 * j + 2]);
                        v.w = __uint_as_float(r[4 * j + 3]);
                        *(float4*)(row + j * 16) = v;
                    }
                }
            }
            __syncthreads();
            #pragma unroll
            for (int p = 0; p < 16; p++) {
                int idx = tid + p * 256;
                int r = idx >> 5, cq = idx & 31;
                float4 v = *(float4*)(sm + r * 528 + cq * 16);
                int n = bn + h * 128 + cq * 4;
                size_t off = (size_t)(bm + mh * 128 + r) * N + n;
                if (BIAS) {
                    float4 bb = *(const float4*)(bias + n);
                    v.x += bb.x; v.y += bb.y; v.z += bb.z; v.w += bb.w;
                }
                if (GELU) {
                    v.x = 0.5f * v.x * (1.0f + erff(v.x * 0.7071067811865476f));
                    v.y = 0.5f * v.y * (1.0f + erff(v.y * 0.7071067811865476f));
                    v.z = 0.5f * v.z * (1.0f + erff(v.z * 0.7071067811865476f));
                    v.w = 0.5f * v.w * (1.0f + erff(v.w * 0.7071067811865476f));
                }
                if (RES) {
                    float4 rr = *(const float4*)(res + off);
                    v.x += rr.x; v.y += rr.y; v.z += rr.z; v.w += rr.w;
                }
                if (OUT_F16) {
                    __half2 h0 = __floats2half2_rn(v.x, v.y);
                    __half2 h1 = __floats2half2_rn(v.z, v.w);
                    uint2 pk;
                    pk.x = *(uint32_t*)&h0;
                    pk.y = *(uint32_t*)&h1;
                    *(uint2*)(((__half*)C) + off) = pk;
                } else {
                    *(float4*)(C + off) = v;
                }
            }
            __syncthreads();
        }
    }

    if (tid == 0) { MBAR_INVAL(mbar0); MBAR_INVAL(mbar0 + 8); MBAR_INVAL(mbar0 + 16); }
    if (wid == 4) {
        asm volatile("tcgen05.dealloc.cta_group::1.sync.aligned.b32 %0, %1;" :: "r"(tmem), "r"(512));
    }
#endif
}

// ---------------- fp16 flash attention (causal), single-S, OCCUPANCY 2 ----------------
// smem: Q 16K | K0 16K | K1 16K | V0 16K | V1 16K | P 32K = 112K (+1K align)
// TMEM (alloc 256/CTA): S 0-127, O 128-191
#define ATT_Q  0
#define ATT_K0 16384
#define ATT_V0 49152
#define ATT_P  81920
#define ATT_SMEM (114688 + 1024)
#define LOG2E 1.4426950408889634f

#define IDESC_S   ((1u << 4) | (16u << 17) | (8u << 24))   // f16, N=128
#define IDESC_PVH ((1u << 4) | ( 8u << 17) | (8u << 24))   // f16, N=64

__global__ void __launch_bounds__(256, 2)
flash_attn_tc(const __half* __restrict__ QKV, const __half* __restrict__ VT,
              __half* __restrict__ ctx) {
#if TC_OK
    extern __shared__ char sm_raw[];
    __shared__ uint32_t s_tmem;
    __shared__ __align__(8) uint64_t s_mbar[2];   // s, pv

    const int tid = threadIdx.x, wid = tid >> 5, lane = tid & 31;
    const int half = wid >> 2;
    const int row  = (wid & 3) * 32 + lane;
    const int qti = gridDim.x - 1 - blockIdx.x;
    const int qt  = qti * 128;
    const int bh  = blockIdx.y;
    const int b   = bh >> 4, h = bh & 15;
    const int base = b * SEQ;
    const int hcol = h * DHEAD;
    const __half* vtb = VT + (size_t)bh * DHEAD * SEQ;

    uint32_t smb_raw = smem_u32(sm_raw);
    uint32_t smb = (smb_raw + 1023u) & ~1023u;
    char* sm = sm_raw + (smb - smb_raw);
    uint32_t mbar_s  = smem_u32(&s_mbar[0]);
    uint32_t mbar_pv = mbar_s + 8;

    if (wid == 4) {
        asm volatile("tcgen05.alloc.cta_group::1.sync.aligned.shared::cta.b32 [%0], %1;"
                     :: "r"(smem_u32(&s_tmem)), "r"(256) : "memory");
    }
    if (tid == 0) { MBAR_INIT(mbar_s, 1); MBAR_INIT(mbar_pv, 1); }
    __syncthreads();
    const uint32_t tmem = s_tmem;

    const int qr = tid >> 3, qg = tid & 7;
    const int ntiles = qti + 1;
    const __half2 qscale = __float2half2_rn(0.125f * LOG2E);

    #define ISSUE_K(kt, kb_off) do { \
        _Pragma("unroll") \
        for (int p = 0; p < 4; p++) { \
            int r = qr + p * 32; \
            CPA16(smb + (kb_off) + SWZ((uint32_t)(r * 128 + qg * 16)), \
                  QKV + (size_t)(base + (kt) * 128 + r) * QKVS + EMB + hcol + qg * 8); \
        } } while (0)
    #define ISSUE_V(kt, vb_off) do { \
        _Pragma("unroll") \
        for (int p = 0; p < 4; p++) { \
            int idx = tid + p * 256; \
            int ck = idx >> 9, rem = idx & 511; \
            int d = rem >> 3, g = rem & 7; \
            CPA16(smb + (vb_off) + (uint32_t)ck * 8192 + SWZ((uint32_t)(d * 128 + g * 16)), \
                  vtb + (size_t)d * SEQ + (kt) * 128 + ck * 64 + g * 8); \
        } } while (0)

    // ---- prologue: Q (scaled, log2 domain); G0={K0,V0}; G1={K1,V1} ----
    #pragma unroll
    for (int p = 0; p < 4; p++) {
        int r = qr + p * 32;
        uint4 v = *(const uint4*)(QKV + (size_t)(base + qt + r) * QKVS + hcol + qg * 8);
        __half2* hv = (__half2*)&v;
        #pragma unroll
        for (int e = 0; e < 4; e++) hv[e] = __hmul2(hv[e], qscale);
        *(uint4*)(sm + ATT_Q + SWZ((uint32_t)(r * 128 + qg * 16))) = v;
    }
    ISSUE_K(0, ATT_K0);
    ISSUE_V(0, ATT_V0);
    CPA_COMMIT();
    if (ntiles > 1) {
        ISSUE_K(1, ATT_K0 + 16384);
        ISSUE_V(1, ATT_V0 + 16384);
    }
    CPA_COMMIT();

    float sum = 0.f;
    const int qrow = qt + row;
    const uint64_t qdesc_base = make_desc_sw128(smb + ATT_Q);

    for (int t = 0; t < ntiles; t++) {
        const int k0 = t * 128;

        // p1: PV(t-1) done -> P + V[(t+1)&1] free; issue V(t+1). Commit always.
        if (t > 0) {
            MBAR_WAIT(mbar_pv, (t - 1) & 1);
            if (t + 1 < ntiles)
                ISSUE_V(t + 1, ATT_V0 + (uint32_t)((t + 1) & 1) * 16384);
        }
        CPA_COMMIT();

        // p2: K(t), V(t) landed (2 newest groups may be pending)
        CPA_WAIT2();
        asm volatile("fence.proxy.async.shared::cta;" ::: "memory");
        __syncthreads();

        // p3: S-MMA(t)
        if (wid == 4 && elect1()) {
            uint64_t bd = make_desc_sw128(smb + ATT_K0 + (uint32_t)(t & 1) * 16384);
            #pragma unroll
            for (int kk = 0; kk < 4; kk++)
                mma_f16_ss(tmem, qdesc_base + kk * 2, bd + kk * 2, IDESC_S, kk ? 1u : 0u);
            asm volatile("tcgen05.commit.cta_group::1.mbarrier::arrive::one.shared::cluster.b64 [%0];"
                         :: "r"(mbar_s) : "memory");
        }

        // p4: wait S
        MBAR_WAIT(mbar_s, t & 1);
        asm volatile("tcgen05.fence::after_thread_sync;" ::: "memory");

        // p5: K(t+2) into K[t&1] (S(t) done reading). Commit always.
        if (t + 2 < ntiles)
            ISSUE_K(t + 2, ATT_K0 + (uint32_t)(t & 1) * 16384);
        CPA_COMMIT();

        // p6: softmax, 2 chunks of 32 cols (low regs)
        #pragma unroll
        for (int ch = 0; ch < 2; ch++) {
            float s[32];
            uint32_t* su = (uint32_t*)s;
            LDTM_X32(su, tmem + half * 64 + ch * 32);
            asm volatile("tcgen05.wait::ld.sync.aligned;" ::: "memory");
            const int kb = k0 + half * 64 + ch * 32;
            if (kb + 31 > qrow) {
                #pragma unroll
                for (int j = 0; j < 32; j++)
                    if (kb + j > qrow) s[j] = -1e30f;
            }
            float ls = 0.f;
            uint32_t hp[16];
            #pragma unroll
            for (int j = 0; j < 16; j++) {
                float p0 = ex2(s[2 * j]);
                float p1 = ex2(s[2 * j + 1]);
                ls += p0 + p1;
                __half2 h2 = __floats2half2_rn(p0, p1);
                hp[j] = *(uint32_t*)&h2;
            }
            sum += ls;
            char* pb = sm + ATT_P + half * 16384;
            #pragma unroll
            for (int g = 0; g < 4; g++) {
                uint4 tt;
                tt.x = hp[4 * g + 0];
                tt.y = hp[4 * g + 1];
                tt.z = hp[4 * g + 2];
                tt.w = hp[4 * g + 3];
                *(uint4*)(pb + SWZ((uint32_t)(row * 128 + ch * 64 + g * 16))) = tt;
            }
        }
        asm volatile("fence.proxy.async.shared::cta;" ::: "memory");
        __syncthreads();

        // p7: PV(t) -> O accumulate
        if (wid == 4 && elect1()) {
            const uint32_t vb = ATT_V0 + (uint32_t)(t & 1) * 16384;
            #pragma unroll
            for (int c = 0; c < 2; c++) {
                uint64_t ad = make_desc_sw128(smb + ATT_P + c * 16384);
                uint64_t bd = make_desc_sw128(smb + vb + c * 8192);
                #pragma unroll
                for (int kk = 0; kk < 4; kk++) {
                    uint32_t en = (t > 0 || c > 0 || kk > 0) ? 1u : 0u;
                    mma_f16_ss(tmem + 128, ad + kk * 2, bd + kk * 2, IDESC_PVH, en);
                }
            }
            asm volatile("tcgen05.commit.cta_group::1.mbarrier::arrive::one.shared::cluster.b64 [%0];"
                         :: "r"(mbar_pv) : "memory");
        }
    }
    #undef ISSUE_K
    #undef ISSUE_V

    // final: wait last PV; exchange sums through dead P region; read O; store
    MBAR_WAIT(mbar_pv, (ntiles - 1) & 1);
    asm volatile("tcgen05.fence::after_thread_sync;" ::: "memory");
    {
        float* ex = (float*)(sm + ATT_P);
        ex[half * 128 + row] = sum;
    }
    __syncthreads();
    float total = sum + ((float*)(sm + ATT_P))[(1 - half) * 128 + row];

    uint32_t part[32];
    LDTM_X32(part, tmem + 128 + half * 32);
    asm volatile("tcgen05.wait::ld.sync.aligned;" ::: "memory");

    {
        float inv = 1.0f / total;
        __half* outp = ctx + (size_t)(base + qrow) * EMB + hcol + half * 32;
        #pragma unroll
        for (int g = 0; g < 4; g++) {
            uint4 v;
            uint32_t* vo = (uint32_t*)&v;
            #pragma unroll
            for (int e = 0; e < 4; e++) {
                __half2 h2 = __floats2half2_rn(
                    __uint_as_float(part[8 * g + 2 * e])     * inv,
                    __uint_as_float(part[8 * g + 2 * e + 1]) * inv);
                vo[e] = *(uint32_t*)&h2;
            }
            *(uint4*)(outp + g * 8) = v;
        }
    }

    __syncthreads();
    if (tid == 0) { MBAR_INVAL(mbar_s); MBAR_INVAL(mbar_pv); }
    if (wid == 4) {
        asm volatile("tcgen05.dealloc.cta_group::1.sync.aligned.b32 %0, %1;" :: "r"(tmem), "r"(256));
    }
#endif
}

// ---------------- launch ----------------
extern "C" void kernel_launch(void* const* d_in, const int* in_sizes, int n_in,
                              void* d_out, int out_size) {
    const float* x     = (const float*)d_in[0];
    const float* Wq    = (const float*)d_in[1];
    const float* Wk    = (const float*)d_in[2];
    const float* Wv    = (const float*)d_in[3];
    const float* Wo    = (const float*)d_in[4];
    const float* bo    = (const float*)d_in[5];
    const float* W1    = (const float*)d_in[6];
    const float* b1    = (const float*)d_in[7];
    const float* W2    = (const float*)d_in[8];
    const float* b2    = (const float*)d_in[9];
    const float* g1    = (const float*)d_in[10];
    const float* beta1 = (const float*)d_in[11];
    const float* g2    = (const float*)d_in[12];
    const float* beta2 = (const float*)d_in[13];
    float* out = (float*)d_out;

    __half *lnx, *qkv, *vt, *ctx, *mid, *wqkv_t, *wo_t, *w1_t, *w2_t;
    float *h;
    cudaGetSymbolAddress((void**)&lnx,    g_lnx);
    cudaGetSymbolAddress((void**)&qkv,    g_qkv);
    cudaGetSymbolAddress((void**)&vt,     g_vt);
    cudaGetSymbolAddress((void**)&ctx,    g_ctx);
    cudaGetSymbolAddress((void**)&h,      g_h);
    cudaGetSymbolAddress((void**)&mid,    g_mid);
    cudaGetSymbolAddress((void**)&wqkv_t, g_wqkv_t);
    cudaGetSymbolAddress((void**)&wo_t,   g_wo_t);
    cudaGetSymbolAddress((void**)&w1_t,   g_w1_t);
    cudaGetSymbolAddress((void**)&w2_t,   g_w2_t);

    cudaFuncSetAttribute(tc_gemm<false,false,false,true >, cudaFuncAttributeMaxDynamicSharedMemorySize, SMEM_DYN);
    cudaFuncSetAttribute(tc_gemm<false,true, true, false>, cudaFuncAttributeMaxDynamicSharedMemorySize, SMEM_DYN);
    cudaFuncSetAttribute(tc_gemm<true, true, false,true >, cudaFuncAttributeMaxDynamicSharedMemorySize, SMEM_DYN);
    cudaFuncSetAttribute(flash_attn_tc, cudaFuncAttributeMaxDynamicSharedMemorySize, ATT_SMEM);

    prep_weights_kernel<<<12288, 256>>>(Wq, Wk, Wv, Wo, W1, W2, wqkv_t, wo_t, w1_t, w2_t);

    layernorm_kernel<<<MTOT, 256>>>(x, g1, beta1, lnx);
    tc_gemm<false,false,false,true><<<dim3(3*EMB/BN, MTOT/BM), 256, SMEM_DYN>>>(
        lnx, wqkv_t, (float*)qkv, MTOT, 3*EMB, EMB, nullptr, nullptr);
    vt_kernel<<<dim3(SEQ/64, BATCH*HEADS), 256>>>(qkv, vt);
    flash_attn_tc<<<dim3(SEQ/128, BATCH*HEADS), 256, ATT_SMEM>>>(qkv, vt, ctx);
    tc_gemm<false,true,true,false><<<dim3(EMB/BN, MTOT/BM), 256, SMEM_DYN>>>(
        ctx, wo_t, h, MTOT, EMB, EMB, bo, x);
    layernorm_kernel<<<MTOT, 256>>>(h, g2, beta2, lnx);
    tc_gemm<true,true,false,true><<<dim3(FFN/BN, MTOT/BM), 256, SMEM_DYN>>>(
        lnx, w1_t, (float*)mid, MTOT, FFN, EMB, b1, nullptr);
    tc_gemm<false,true,true,false><<<dim3(EMB/BN, MTOT/BM), 256, SMEM_DYN>>>(
        mid, w2_t, out, MTOT, EMB, FFN, b2, h);
}

// round 17
// speedup vs baseline: 1.0364x; 1.0364x over previous
#include <cuda_runtime.h>
#include <cuda_fp16.h>
#include <math.h>
#include <stdint.h>

// Problem constants
#define BATCH 4
#define SEQ   2048
#define EMB   1024
#define HEADS 16
#define DHEAD 64
#define MTOT  (BATCH*SEQ)      // 8192
#define FFN   (4*EMB)          // 4096

#if defined(__CUDA_ARCH__) && (defined(__CUDA_ARCH_FEAT_SM103_ALL) || defined(__CUDA_ARCH_FEAT_SM100_ALL))
#define TC_OK 1
#else
#define TC_OK 0
#endif

// ---------------- scratch (no allocs allowed) ----------------
__device__ __half g_lnx [(size_t)MTOT*EMB];
__device__ __half g_qkv [(size_t)MTOT*3*EMB];
__device__ __half g_vt  [(size_t)BATCH*HEADS*DHEAD*SEQ];   // V^T per (b,h): [64 d][2048 s]
__device__ __half g_ctx [(size_t)MTOT*EMB];
__device__ float  g_h   [(size_t)MTOT*EMB];
__device__ __half g_mid [(size_t)MTOT*FFN];
__device__ __half g_wqkv_t[(size_t)3*EMB*EMB];
__device__ __half g_wo_t  [(size_t)EMB*EMB];
__device__ __half g_w1_t  [(size_t)FFN*EMB];
__device__ __half g_w2_t  [(size_t)EMB*FFN];

// ---------------- helpers ----------------
__device__ __forceinline__ uint32_t smem_u32(const void* p) {
    uint32_t a;
    asm("{ .reg .u64 t; cvta.to.shared.u64 t, %1; cvt.u32.u64 %0, t; }" : "=r"(a) : "l"(p));
    return a;
}
__device__ __forceinline__ float ex2(float x) {
    float r;
    asm("ex2.approx.f32 %0, %1;" : "=f"(r) : "f"(x));
    return r;
}
#define SWZ(o) ((o) ^ (((o) >> 3) & 0x70))

#define MBAR_INIT(a, c) asm volatile("mbarrier.init.shared.b64 [%0], %1;" :: "r"(a), "r"(c) : "memory")
#define MBAR_INVAL(a)   asm volatile("mbarrier.inval.shared.b64 [%0];" :: "r"(a) : "memory")
#define MBAR_WAIT(a, ph) do { \
    uint32_t _m = (a); uint32_t _p = (ph); uint32_t _d; \
    asm volatile("{ .reg .pred p; mbarrier.try_wait.parity.acquire.cta.shared::cta.b64 p, [%1], %2; selp.b32 %0,1,0,p; }" \
        : "=r"(_d) : "r"(_m), "r"(_p) : "memory"); \
    if (!_d) { \
        asm volatile("{ .reg .pred P1; WL_%=: mbarrier.try_wait.parity.acquire.cta.shared::cta.b64 P1, [%0], %1, 0x989680; @P1 bra.uni WD_%=; bra.uni WL_%=; WD_%=: }" \
            :: "r"(_m), "r"(_p) : "memory"); \
    } } while (0)

#define CPA16(dst, src) asm volatile("cp.async.cg.shared.global [%0], [%1], 16;" :: "r"(dst), "l"(src) : "memory")
#define CPA_COMMIT() asm volatile("cp.async.commit_group;" ::: "memory")
#define CPA_WAIT2()  asm volatile("cp.async.wait_group 2;" ::: "memory")
#define CPA_WAIT1()  asm volatile("cp.async.wait_group 1;" ::: "memory")
#define CPA_WAIT0()  asm volatile("cp.async.wait_group 0;" ::: "memory")

#if TC_OK
__device__ __forceinline__ uint32_t elect1() {
    uint32_t p;
    asm volatile("{ .reg .pred p; elect.sync _|p, 0xFFFFFFFF; selp.b32 %0,1,0,p; }" : "=r"(p));
    return p;
}
// K-major SW128: LBO=1, SBO=64 (proven)
__device__ __forceinline__ uint64_t make_desc_sw128(uint32_t addr) {
    const uint64_t base = (2ull << 61) | (1ull << 46) | (64ull << 32) | (1ull << 16);
    return base | ((uint64_t)(addr >> 4) & 0x3FFF);
}
#define LDTM_X32(r, addr) \
    asm volatile("tcgen05.ld.sync.aligned.32x32b.x32.b32 " \
        "{%0,%1,%2,%3,%4,%5,%6,%7,%8,%9,%10,%11,%12,%13,%14,%15," \
        "%16,%17,%18,%19,%20,%21,%22,%23,%24,%25,%26,%27,%28,%29,%30,%31}, [%32];" \
        : "=r"((r)[0]),"=r"((r)[1]),"=r"((r)[2]),"=r"((r)[3]),"=r"((r)[4]),"=r"((r)[5]),"=r"((r)[6]),"=r"((r)[7]), \
          "=r"((r)[8]),"=r"((r)[9]),"=r"((r)[10]),"=r"((r)[11]),"=r"((r)[12]),"=r"((r)[13]),"=r"((r)[14]),"=r"((r)[15]), \
          "=r"((r)[16]),"=r"((r)[17]),"=r"((r)[18]),"=r"((r)[19]),"=r"((r)[20]),"=r"((r)[21]),"=r"((r)[22]),"=r"((r)[23]), \
          "=r"((r)[24]),"=r"((r)[25]),"=r"((r)[26]),"=r"((r)[27]),"=r"((r)[28]),"=r"((r)[29]),"=r"((r)[30]),"=r"((r)[31]) \
        : "r"(addr))

__device__ __forceinline__ void mma_f16_ss(uint32_t d, uint64_t ad, uint64_t bd,
                                           uint32_t idesc, uint32_t en) {
    asm volatile("{\n\t.reg .pred p;\n\tsetp.ne.u32 p, %5, 0;\n\t"
        "tcgen05.mma.cta_group::1.kind::f16 [%0], %1, %2, %3, {%4,%4,%4,%4}, p;\n\t}"
        :: "r"(d), "l"(ad), "l"(bd), "r"(idesc), "r"(0u), "r"(en) : "memory");
}
#endif

// ---------------- fused: LN1 (blocks 0..8191) + weight prep (blocks 8192..20479) ----------------
#define QKVS (3*EMB)
__device__ __forceinline__ float warp_sum(float v) {
    #pragma unroll
    for (int o = 16; o > 0; o >>= 1) v += __shfl_xor_sync(0xffffffffu, v, o);
    return v;
}

__global__ void prep_ln_kernel(const float* __restrict__ x,
                               const float* __restrict__ gamma,
                               const float* __restrict__ beta,
                               __half* __restrict__ lnout,
                               const float* __restrict__ Wq, const float* __restrict__ Wk,
                               const float* __restrict__ Wv, const float* __restrict__ Wo,
                               const float* __restrict__ W1, const float* __restrict__ W2,
                               __half* __restrict__ wqkv_t, __half* __restrict__ wo_t,
                               __half* __restrict__ w1_t, __half* __restrict__ w2_t) {
    __shared__ float t[32][33];
    __shared__ float sh[2][8];
    if (blockIdx.x < MTOT) {
        // ---- LayerNorm row ----
        const int row = blockIdx.x;
        const float* xr = x + (size_t)row * EMB;
        float s = 0.f, s2 = 0.f;
        for (int i = threadIdx.x; i < EMB; i += blockDim.x) {
            float v = xr[i];
            s += v; s2 += v * v;
        }
        s = warp_sum(s); s2 = warp_sum(s2);
        int lane = threadIdx.x & 31, wid = threadIdx.x >> 5;
        if (lane == 0) { sh[0][wid] = s; sh[1][wid] = s2; }
        __syncthreads();
        if (wid == 0) {
            float a = (lane < 8) ? sh[0][lane] : 0.f;
            float b = (lane < 8) ? sh[1][lane] : 0.f;
            a = warp_sum(a); b = warp_sum(b);
            if (lane == 0) { sh[0][0] = a; sh[1][0] = b; }
        }
        __syncthreads();
        float mean = sh[0][0] * (1.0f / EMB);
        float var  = sh[1][0] * (1.0f / EMB) - mean * mean;
        float inv  = rsqrtf(var + 1e-5f);
        __half* outr = lnout + (size_t)row * EMB;
        for (int i = threadIdx.x; i < EMB; i += blockDim.x) {
            outr[i] = __float2half_rn(gamma[i] * ((xr[i] - mean) * inv) + beta[i]);
        }
    } else {
        // ---- weight transpose tile ----
        int id = blockIdx.x - MTOT;
        const float* W; __half* WT; int K, N, n0, k0;
        if (id < 4096) {
            int w = id >> 10; id &= 1023;
            K = EMB; N = EMB;
            W  = (w == 0) ? Wq : (w == 1) ? Wk : (w == 2) ? Wv : Wo;
            WT = (w < 3) ? (wqkv_t + (size_t)w * EMB * EMB) : wo_t;
            n0 = (id & 31) * 32; k0 = (id >> 5) * 32;
        } else if (id < 8192) {
            id -= 4096; K = EMB; N = FFN; W = W1; WT = w1_t;
            n0 = (id & 127) * 32; k0 = (id >> 7) * 32;
        } else {
            id -= 8192; K = FFN; N = EMB; W = W2; WT = w2_t;
            n0 = (id & 31) * 32; k0 = (id >> 5) * 32;
        }
        const int tx = threadIdx.x & 31, ty = threadIdx.x >> 5;
        #pragma unroll
        for (int j = 0; j < 32; j += 8)
            t[ty + j][tx] = W[(size_t)(k0 + ty + j) * N + n0 + tx];
        __syncthreads();
        #pragma unroll
        for (int j = 0; j < 32; j += 8)
            WT[(size_t)(n0 + ty + j) * K + k0 + tx] = __float2half_rn(t[tx][ty + j]);
    }
}

// ---------------- V transpose: QKV V-part -> [bh][64 d][2048 s] fp16 ----------------
__global__ void vt_kernel(const __half* __restrict__ QKV, __half* __restrict__ vt) {
    __shared__ __align__(16) __half t[64][72];
    const int tid = threadIdx.x;
    const int bh = blockIdx.y, s0 = blockIdx.x * 64;
    const int b = bh >> 4, h = bh & 15;
    const __half* src = QKV + (size_t)(b * SEQ + s0) * QKVS + 2 * EMB + h * DHEAD;
    #pragma unroll
    for (int p = 0; p < 2; p++) {
        int idx = tid + p * 256;
        int r = idx >> 3, g = idx & 7;
        *(uint4*)&t[r][g * 8] = *(const uint4*)(src + (size_t)r * QKVS + g * 8);
    }
    __syncthreads();
    __half* dst = vt + (size_t)bh * DHEAD * SEQ + s0;
    #pragma unroll
    for (int p = 0; p < 2; p++) {
        int idx = tid + p * 256;
        int d = idx >> 3, g = idx & 7;
        __half tmp[8];
        #pragma unroll
        for (int i = 0; i < 8; i++) tmp[i] = t[g * 8 + i][d];
        *(uint4*)(dst + (size_t)d * SEQ + g * 8) = *(uint4*)tmp;
    }
}

// ---------------- LayerNorm -> fp16 out (standalone, for LN2) ----------------
__global__ void layernorm_kernel(const float* __restrict__ x,
                                 const float* __restrict__ gamma,
                                 const float* __restrict__ beta,
                                 __half* __restrict__ out) {
    const int row = blockIdx.x;
    const float* xr = x + (size_t)row * EMB;
    float s = 0.f, s2 = 0.f;
    for (int i = threadIdx.x; i < EMB; i += blockDim.x) {
        float v = xr[i];
        s += v; s2 += v * v;
    }
    s = warp_sum(s); s2 = warp_sum(s2);
    __shared__ float sh[2][8];
    int lane = threadIdx.x & 31, wid = threadIdx.x >> 5;
    if (lane == 0) { sh[0][wid] = s; sh[1][wid] = s2; }
    __syncthreads();
    if (wid == 0) {
        float a = (lane < 8) ? sh[0][lane] : 0.f;
        float b = (lane < 8) ? sh[1][lane] : 0.f;
        a = warp_sum(a); b = warp_sum(b);
        if (lane == 0) { sh[0][0] = a; sh[1][0] = b; }
    }
    __syncthreads();
    float mean = sh[0][0] * (1.0f / EMB);
    float var  = sh[1][0] * (1.0f / EMB) - mean * mean;
    float inv  = rsqrtf(var + 1e-5f);
    __half* outr = out + (size_t)row * EMB;
    for (int i = threadIdx.x; i < EMB; i += blockDim.x) {
        outr[i] = __float2half_rn(gamma[i] * ((xr[i] - mean) * inv) + beta[i]);
    }
}

// ---------------- tcgen05 fp16 GEMM: 256x256 tile, BK=64, 3-stage cp.async (R13 proven) ----------------
#define BM 256
#define BN 256
#define BK 64
#define ABYTES (BM*128)
#define BBYTES (BN*128)
#define BUFBYTES (ABYTES+BBYTES)
#define NSTAGE 3
#define SMEM_DYN (NSTAGE*BUFBYTES + 1024)

#define IDESC_F16 ((1u << 4) | ((BN / 8) << 17) | (8u << 24))

template<bool GELU, bool BIAS, bool RES, bool OUT_F16>
__global__ void __launch_bounds__(256, 1)
tc_gemm(const __half* __restrict__ A, const __half* __restrict__ BT,
        float* __restrict__ C, int M, int N, int K,
        const float* __restrict__ bias, const float* __restrict__ res) {
#if TC_OK
    extern __shared__ char sm_raw[];
    __shared__ uint32_t s_tmem;
    __shared__ __align__(8) uint64_t s_mbar[NSTAGE];

    const int tid = threadIdx.x, wid = tid >> 5, lane = tid & 31;
    const int bm = blockIdx.y * BM, bn = blockIdx.x * BN;

    uint32_t smb_raw = smem_u32(sm_raw);
    uint32_t smb = (smb_raw + 1023u) & ~1023u;
    char* sm = sm_raw + (smb - smb_raw);
    uint32_t mbar0 = smem_u32(&s_mbar[0]);

    if (wid == 4) {
        asm volatile("tcgen05.alloc.cta_group::1.sync.aligned.shared::cta.b32 [%0], %1;"
                     :: "r"(smem_u32(&s_tmem)), "r"(512) : "memory");
    }
    if (tid == 0) { MBAR_INIT(mbar0, 1); MBAR_INIT(mbar0 + 8, 1); MBAR_INIT(mbar0 + 16, 1); }
    __syncthreads();
    const uint32_t tmem = s_tmem;

    const int am = tid >> 3, akq = tid & 7;
    const uint32_t sw0 = SWZ((uint32_t)(am * 128 + akq * 16));
    const int KIT = K / BK;

    #define ISSUE(j, stb) do { \
        const __half* ap = A + (size_t)(bm + am) * K + (j) * BK + akq * 8; \
        _Pragma("unroll") \
        for (int p = 0; p < 8; p++) \
            CPA16(smb + (stb) + p * 4096 + sw0, ap + (size_t)(p * 32) * K); \
        const __half* bp = BT + (size_t)(bn + am) * K + (j) * BK + akq * 8; \
        _Pragma("unroll") \
        for (int p = 0; p < 8; p++) \
            CPA16(smb + (stb) + ABYTES + p * 4096 + sw0, bp + (size_t)(p * 32) * K); \
    } while (0)

    #pragma unroll
    for (int j = 0; j < NSTAGE; j++) {
        ISSUE(j, (uint32_t)j * BUFBYTES);
        CPA_COMMIT();
    }

    for (int i = 0; i < KIT; i++) {
        const int s3 = i % NSTAGE;
        const uint32_t stb = (uint32_t)s3 * BUFBYTES;

        CPA_WAIT2();
        __syncthreads();
        asm volatile("fence.proxy.async.shared::cta;" ::: "memory");

        if (wid == 4) {
            uint64_t ad0 = make_desc_sw128(smb + stb);
            uint64_t ad1 = make_desc_sw128(smb + stb + 16384);
            uint64_t bd  = make_desc_sw128(smb + stb + ABYTES);
            if (elect1()) {
                #pragma unroll
                for (int kk = 0; kk < 4; kk++) {
                    uint32_t en = (i > 0 || kk > 0) ? 1u : 0u;
                    mma_f16_ss(tmem, ad0 + kk * 2, bd + kk * 2, IDESC_F16, en);
                }
                #pragma unroll
                for (int kk = 0; kk < 4; kk++) {
                    uint32_t en = (i > 0 || kk > 0) ? 1u : 0u;
                    mma_f16_ss(tmem + 256, ad1 + kk * 2, bd + kk * 2, IDESC_F16, en);
                }
                asm volatile("tcgen05.commit.cta_group::1.mbarrier::arrive::one.shared::cluster.b64 [%0];"
                             :: "r"(mbar0 + 8 * s3) : "memory");
            }
        }

        const int j = i + NSTAGE;
        if (j < KIT) {
            MBAR_WAIT(mbar0 + 8 * s3, (i / NSTAGE) & 1);
            ISSUE(j, stb);
        }
        CPA_COMMIT();
    }
    #undef ISSUE

    MBAR_WAIT(mbar0 + 8 * ((KIT - 1) % NSTAGE), ((KIT - 1) / NSTAGE) & 1);
    asm volatile("tcgen05.fence::after_thread_sync;" ::: "memory");
    __syncthreads();

    // R13 epilogue: 2 M-halves x 2 column-halves, staged via padded SMEM (warps 0-3)
    #pragma unroll
    for (int mh = 0; mh < 2; mh++) {
        #pragma unroll
        for (int h = 0; h < 2; h++) {
            if (wid < 4) {
                #pragma unroll
                for (int c = 0; c < 4; c++) {
                    uint32_t r[32];
                    LDTM_X32(r, tmem + mh * 256 + h * 128 + c * 32);
                    asm volatile("tcgen05.wait::ld.sync.aligned;" ::: "memory");
                    char* row = sm + (wid * 32 + lane) * 528 + c * 128;
                    #pragma unroll
                    for (int j = 0; j < 8; j++) {
                        float4 v;
                        v.x = __uint_as_float(r[4 * j + 0]);
                        v.y = __uint_as_float(r[4 * j + 1]);
                        v.z = __uint_as_float(r[4 * j + 2]);
                        v.w = __uint_as_float(r[4 * j + 3]);
                        *(float4*)(row + j * 16) = v;
                    }
                }
            }
            __syncthreads();
            #pragma unroll
            for (int p = 0; p < 16; p++) {
                int idx = tid + p * 256;
                int r = idx >> 5, cq = idx & 31;
                float4 v = *(float4*)(sm + r * 528 + cq * 16);
                int n = bn + h * 128 + cq * 4;
                size_t off = (size_t)(bm + mh * 128 + r) * N + n;
                if (BIAS) {
                    float4 bb = *(const float4*)(bias + n);
                    v.x += bb.x; v.y += bb.y; v.z += bb.z; v.w += bb.w;
                }
                if (GELU) {
                    v.x = 0.5f * v.x * (1.0f + erff(v.x * 0.7071067811865476f));
                    v.y = 0.5f * v.y * (1.0f + erff(v.y * 0.7071067811865476f));
                    v.z = 0.5f * v.z * (1.0f + erff(v.z * 0.7071067811865476f));
                    v.w = 0.5f * v.w * (1.0f + erff(v.w * 0.7071067811865476f));
                }
                if (RES) {
                    float4 rr = *(const float4*)(res + off);
                    v.x += rr.x; v.y += rr.y; v.z += rr.z; v.w += rr.w;
                }
                if (OUT_F16) {
                    __half2 h0 = __floats2half2_rn(v.x, v.y);
                    __half2 h1 = __floats2half2_rn(v.z, v.w);
                    uint2 pk;
                    pk.x = *(uint32_t*)&h0;
                    pk.y = *(uint32_t*)&h1;
                    *(uint2*)(((__half*)C) + off) = pk;
                } else {
                    *(float4*)(C + off) = v;
                }
            }
            __syncthreads();
        }
    }

    if (tid == 0) { MBAR_INVAL(mbar0); MBAR_INVAL(mbar0 + 8); MBAR_INVAL(mbar0 + 16); }
    if (wid == 4) {
        asm volatile("tcgen05.dealloc.cta_group::1.sync.aligned.b32 %0, %1;" :: "r"(tmem), "r"(512));
    }
#endif
}

// ---------------- all-fp16 flash attention (causal), pre-transposed V (R13 proven) ----------------
// smem: Q 16K | K0 16K | K1 16K | V0 16K | V1 16K | P 32K = 112K
// TMEM (alloc 512): S0 0-127, S1 128-255, O 256-319
#define ATT_Q  0
#define ATT_K0 16384
#define ATT_V0 49152
#define ATT_P  81920
#define ATT_SMEM (114688 + 1024)
#define LOG2E 1.4426950408889634f

#define IDESC_S   ((1u << 4) | (16u << 17) | (8u << 24))   // f16, N=128
#define IDESC_PVH ((1u << 4) | ( 8u << 17) | (8u << 24))   // f16, N=64

__global__ void __launch_bounds__(256, 1)
flash_attn_tc(const __half* __restrict__ QKV, const __half* __restrict__ VT,
              __half* __restrict__ ctx) {
#if TC_OK
    extern __shared__ char sm_raw[];
    __shared__ uint32_t s_tmem;
    __shared__ __align__(8) uint64_t s_mbar[3];   // s0, s1, pv
    __shared__ float s_rsum[2][128];

    const int tid = threadIdx.x, wid = tid >> 5, lane = tid & 31;
    const int half = wid >> 2;
    const int row  = (wid & 3) * 32 + lane;
    const int qti = gridDim.x - 1 - blockIdx.x;
    const int qt  = qti * 128;
    const int bh  = blockIdx.y;
    const int b   = bh >> 4, h = bh & 15;
    const int base = b * SEQ;
    const int hcol = h * DHEAD;
    const __half* vtb = VT + (size_t)bh * DHEAD * SEQ;

    uint32_t smb_raw = smem_u32(sm_raw);
    uint32_t smb = (smb_raw + 1023u) & ~1023u;
    char* sm = sm_raw + (smb - smb_raw);
    uint32_t mbar0 = smem_u32(&s_mbar[0]);

    if (wid == 4) {
        asm volatile("tcgen05.alloc.cta_group::1.sync.aligned.shared::cta.b32 [%0], %1;"
                     :: "r"(smem_u32(&s_tmem)), "r"(512) : "memory");
    }
    if (tid == 0) { MBAR_INIT(mbar0, 1); MBAR_INIT(mbar0 + 8, 1); MBAR_INIT(mbar0 + 16, 1); }
    __syncthreads();
    const uint32_t tmem = s_tmem;

    const int qr = tid >> 3, qg = tid & 7;
    const int ntiles = qti + 1;
    const __half2 qscale = __float2half2_rn(0.125f * LOG2E);

    #define ISSUE_K(kt, kb_off) do { \
        _Pragma("unroll") \
        for (int p = 0; p < 4; p++) { \
            int r = qr + p * 32; \
            CPA16(smb + (kb_off) + SWZ((uint32_t)(r * 128 + qg * 16)), \
                  QKV + (size_t)(base + (kt) * 128 + r) * QKVS + EMB + hcol + qg * 8); \
        } } while (0)
    #define ISSUE_V(kt, vb_off) do { \
        _Pragma("unroll") \
        for (int p = 0; p < 4; p++) { \
            int idx = tid + p * 256; \
            int ck = idx >> 9, rem = idx & 511; \
            int d = rem >> 3, g = rem & 7; \
            CPA16(smb + (vb_off) + (uint32_t)ck * 8192 + SWZ((uint32_t)(d * 128 + g * 16)), \
                  vtb + (size_t)d * SEQ + (kt) * 128 + ck * 64 + g * 8); \
        } } while (0)

    // ---- prologue ----
    #pragma unroll
    for (int p = 0; p < 4; p++) {
        int r = qr + p * 32;
        uint4 v = *(const uint4*)(QKV + (size_t)(base + qt + r) * QKVS + hcol + qg * 8);
        __half2* hv = (__half2*)&v;
        #pragma unroll
        for (int e = 0; e < 4; e++) hv[e] = __hmul2(hv[e], qscale);
        *(uint4*)(sm + ATT_Q + SWZ((uint32_t)(r * 128 + qg * 16))) = v;
    }
    ISSUE_K(0, ATT_K0);
    ISSUE_V(0, ATT_V0);
    CPA_COMMIT();
    if (ntiles > 1) {
        ISSUE_K(1, ATT_K0 + 16384);
        ISSUE_V(1, ATT_V0 + 16384);
    }
    CPA_COMMIT();

    if (ntiles > 1) CPA_WAIT1(); else CPA_WAIT0();
    asm volatile("fence.proxy.async.shared::cta;" ::: "memory");
    __syncthreads();
    if (wid == 4 && elect1()) {
        uint64_t ad = make_desc_sw128(smb + ATT_Q);
        uint64_t bd = make_desc_sw128(smb + ATT_K0);
        #pragma unroll
        for (int kk = 0; kk < 4; kk++)
            mma_f16_ss(tmem, ad + kk * 2, bd + kk * 2, IDESC_S, kk ? 1u : 0u);
        asm volatile("tcgen05.commit.cta_group::1.mbarrier::arrive::one.shared::cluster.b64 [%0];"
                     :: "r"(mbar0) : "memory");
    }

    float sum = 0.f;
    const int qrow = qt + row;

    for (int t = 0; t < ntiles; t++) {
        const int k0 = t * 128;

        MBAR_WAIT(mbar0 + 8 * (t & 1), (t >> 1) & 1);
        asm volatile("tcgen05.fence::after_thread_sync;" ::: "memory");
        float s[64];
        uint32_t* su = (uint32_t*)s;
        LDTM_X32(su,      tmem + (uint32_t)(t & 1) * 128 + half * 64);
        LDTM_X32(su + 32, tmem + (uint32_t)(t & 1) * 128 + half * 64 + 32);
        asm volatile("tcgen05.wait::ld.sync.aligned;" ::: "memory");

        if (t > 0) {
            MBAR_WAIT(mbar0 + 16, (t - 1) & 1);
            if (t + 1 < ntiles)
                ISSUE_V(t + 1, ATT_V0 + (uint32_t)((t + 1) & 1) * 16384);
        }
        CPA_COMMIT();

        if (t + 1 < ntiles) CPA_WAIT1(); else CPA_WAIT0();
        asm volatile("fence.proxy.async.shared::cta;" ::: "memory");
        __syncthreads();
        if (t + 1 < ntiles) {
            const uint32_t nkbuf = ATT_K0 + (uint32_t)((t + 1) & 1) * 16384;
            if (wid == 4 && elect1()) {
                uint64_t ad = make_desc_sw128(smb + ATT_Q);
                uint64_t bd = make_desc_sw128(smb + nkbuf);
                #pragma unroll
                for (int kk = 0; kk < 4; kk++)
                    mma_f16_ss(tmem + (uint32_t)((t + 1) & 1) * 128, ad + kk * 2, bd + kk * 2,
                               IDESC_S, kk ? 1u : 0u);
                asm volatile("tcgen05.commit.cta_group::1.mbarrier::arrive::one.shared::cluster.b64 [%0];"
                             :: "r"(mbar0 + 8 * ((t + 1) & 1)) : "memory");
            }
            if (t + 2 < ntiles)
                ISSUE_K(t + 2, ATT_K0 + (uint32_t)(t & 1) * 16384);
            CPA_COMMIT();
        }

        const int kb = k0 + half * 64;
        if (kb + 63 > qrow) {
            #pragma unroll
            for (int j = 0; j < 64; j++)
                if (kb + j > qrow) s[j] = -1e30f;
        }
        float ls = 0.f;
        uint32_t hp[32];
        #pragma unroll
        for (int j = 0; j < 32; j++) {
            float p0 = ex2(s[2 * j]);
            float p1 = ex2(s[2 * j + 1]);
            ls += p0 + p1;
            __half2 h2 = __floats2half2_rn(p0, p1);
            hp[j] = *(uint32_t*)&h2;
        }
        sum += ls;

        {
            char* pb = sm + ATT_P + half * 16384;
            #pragma unroll
            for (int g = 0; g < 8; g++) {
                uint4 tt;
                tt.x = hp[4 * g + 0];
                tt.y = hp[4 * g + 1];
                tt.z = hp[4 * g + 2];
                tt.w = hp[4 * g + 3];
                *(uint4*)(pb + SWZ((uint32_t)(row * 128 + g * 16))) = tt;
            }
        }
        asm volatile("fence.proxy.async.shared::cta;" ::: "memory");
        __syncthreads();

        if (wid == 4 && elect1()) {
            const uint32_t vb = ATT_V0 + (uint32_t)(t & 1) * 16384;
            #pragma unroll
            for (int c = 0; c < 2; c++) {
                uint64_t ad = make_desc_sw128(smb + ATT_P + c * 16384);
                uint64_t bd = make_desc_sw128(smb + vb + c * 8192);
                #pragma unroll
                for (int kk = 0; kk < 4; kk++) {
                    uint32_t en = (t > 0 || c > 0 || kk > 0) ? 1u : 0u;
                    mma_f16_ss(tmem + 256, ad + kk * 2, bd + kk * 2, IDESC_PVH, en);
                }
            }
            asm volatile("tcgen05.commit.cta_group::1.mbarrier::arrive::one.shared::cluster.b64 [%0];"
                         :: "r"(mbar0 + 16) : "memory");
        }
    }
    #undef ISSUE_K
    #undef ISSUE_V

    MBAR_WAIT(mbar0 + 16, (ntiles - 1) & 1);
    asm volatile("tcgen05.fence::after_thread_sync;" ::: "memory");
    s_rsum[half][row] = sum;
    __syncthreads();
    float total = sum + s_rsum[1 - half][row];

    uint32_t part[32];
    LDTM_X32(part, tmem + 256 + half * 32);
    asm volatile("tcgen05.wait::ld.sync.aligned;" ::: "memory");

    {
        float inv = 1.0f / total;
        __half* outp = ctx + (size_t)(base + qrow) * EMB + hcol + half * 32;
        #pragma unroll
        for (int g = 0; g < 4; g++) {
            uint4 v;
            uint32_t* vo = (uint32_t*)&v;
            #pragma unroll
            for (int e = 0; e < 4; e++) {
                __half2 h2 = __floats2half2_rn(
                    __uint_as_float(part[8 * g + 2 * e])     * inv,
                    __uint_as_float(part[8 * g + 2 * e + 1]) * inv);
                vo[e] = *(uint32_t*)&h2;
            }
            *(uint4*)(outp + g * 8) = v;
        }
    }

    __syncthreads();
    if (tid == 0) { MBAR_INVAL(mbar0); MBAR_INVAL(mbar0 + 8); MBAR_INVAL(mbar0 + 16); }
    if (wid == 4) {
        asm volatile("tcgen05.dealloc.cta_group::1.sync.aligned.b32 %0, %1;" :: "r"(tmem), "r"(512));
    }
#endif
}

// ---------------- launch ----------------
extern "C" void kernel_launch(void* const* d_in, const int* in_sizes, int n_in,
                              void* d_out, int out_size) {
    const float* x     = (const float*)d_in[0];
    const float* Wq    = (const float*)d_in[1];
    const float* Wk    = (const float*)d_in[2];
    const float* Wv    = (const float*)d_in[3];
    const float* Wo    = (const float*)d_in[4];
    const float* bo    = (const float*)d_in[5];
    const float* W1    = (const float*)d_in[6];
    const float* b1    = (const float*)d_in[7];
    const float* W2    = (const float*)d_in[8];
    const float* b2    = (const float*)d_in[9];
    const float* g1    = (const float*)d_in[10];
    const float* beta1 = (const float*)d_in[11];
    const float* g2    = (const float*)d_in[12];
    const float* beta2 = (const float*)d_in[13];
    float* out = (float*)d_out;

    __half *lnx, *qkv, *vt, *ctx, *mid, *wqkv_t, *wo_t, *w1_t, *w2_t;
    float *h;
    cudaGetSymbolAddress((void**)&lnx,    g_lnx);
    cudaGetSymbolAddress((void**)&qkv,    g_qkv);
    cudaGetSymbolAddress((void**)&vt,     g_vt);
    cudaGetSymbolAddress((void**)&ctx,    g_ctx);
    cudaGetSymbolAddress((void**)&h,      g_h);
    cudaGetSymbolAddress((void**)&mid,    g_mid);
    cudaGetSymbolAddress((void**)&wqkv_t, g_wqkv_t);
    cudaGetSymbolAddress((void**)&wo_t,   g_wo_t);
    cudaGetSymbolAddress((void**)&w1_t,   g_w1_t);
    cudaGetSymbolAddress((void**)&w2_t,   g_w2_t);

    cudaFuncSetAttribute(tc_gemm<false,false,false,true >, cudaFuncAttributeMaxDynamicSharedMemorySize, SMEM_DYN);
    cudaFuncSetAttribute(tc_gemm<false,true, true, false>, cudaFuncAttributeMaxDynamicSharedMemorySize, SMEM_DYN);
    cudaFuncSetAttribute(tc_gemm<true, true, false,true >, cudaFuncAttributeMaxDynamicSharedMemorySize, SMEM_DYN);
    cudaFuncSetAttribute(flash_attn_tc, cudaFuncAttributeMaxDynamicSharedMemorySize, ATT_SMEM);

    // fused LN1 + weight prep (independent work, one launch)
    prep_ln_kernel<<<MTOT + 12288, 256>>>(x, g1, beta1, lnx,
                                          Wq, Wk, Wv, Wo, W1, W2,
                                          wqkv_t, wo_t, w1_t, w2_t);
    tc_gemm<false,false,false,true><<<dim3(3*EMB/BN, MTOT/BM), 256, SMEM_DYN>>>(
        lnx, wqkv_t, (float*)qkv, MTOT, 3*EMB, EMB, nullptr, nullptr);
    vt_kernel<<<dim3(SEQ/64, BATCH*HEADS), 256>>>(qkv, vt);
    flash_attn_tc<<<dim3(SEQ/128, BATCH*HEADS), 256, ATT_SMEM>>>(qkv, vt, ctx);
    tc_gemm<false,true,true,false><<<dim3(EMB/BN, MTOT/BM), 256, SMEM_DYN>>>(
        ctx, wo_t, h, MTOT, EMB, EMB, bo, x);
    layernorm_kernel<<<MTOT, 256>>>(h, g2, beta2, lnx);
    tc_gemm<true,true,false,true><<<dim3(FFN/BN, MTOT/BM), 256, SMEM_DYN>>>(
        lnx, w1_t, (float*)mid, MTOT, FFN, EMB, b1, nullptr);
    tc_gemm<false,true,true,false><<<dim3(EMB/BN, MTOT/BM), 256, SMEM_DYN>>>(
        mid, w2_t, out, MTOT, EMB, FFN, b2, h);
}